// round 2
// baseline (speedup 1.0000x reference)
#include <cuda_runtime.h>

#define V 4096
#define T 4096
#define FW 5
#define BATCH 64
#define SLEN 512
#define NROWS (BATCH * SLEN)   // 32768
#define CDIM (V * FW)          // 20480

// Scratch: transposed weights Wt[k][v][t]  (t contiguous -> coalesced gathers)
__device__ float g_Wt[(size_t)FW * V * T];
// Per-row entropy contributions (deterministic final reduction, no atomics)
__device__ float g_rowent[NROWS];

// ---------------------------------------------------------------------------
// Kernel 1: transpose W[t][v][k] -> Wt[k][v][t]
// Treat input as A[t][c], c = v*5 + k  (4096 x 20480). Classic smem tile.
// ---------------------------------------------------------------------------
__global__ __launch_bounds__(256) void transpose_k(const float* __restrict__ W) {
    __shared__ float tile[32][33];
    int c0 = blockIdx.x << 5;
    int t0 = blockIdx.y << 5;
    int tx = threadIdx.x;   // 0..31
    int ty = threadIdx.y;   // 0..7

#pragma unroll
    for (int j = 0; j < 4; j++) {
        int t = t0 + ty + j * 8;
        tile[ty + j * 8][tx] = W[(size_t)t * CDIM + c0 + tx];
    }
    __syncthreads();
#pragma unroll
    for (int j = 0; j < 4; j++) {
        int c = c0 + ty + j * 8;
        int v = c / 5;
        int k = c - v * 5;
        g_Wt[((size_t)k * V + v) * T + t0 + tx] = tile[tx][ty + j * 8];
    }
}

// ---------------------------------------------------------------------------
// Kernel 2: one block per output row (b,s). 256 threads x 16 t-values each.
// fp32 logits in reference summation order; then reproduce the reference's
// QUANTIZED log_softmax values lp = (l - m) - logS0 (fp32) and argmax over
// lp with first-index tie breaking (ties created by fp32 quantization at
// the ~2^-20 grid are what the reference argmax sees).
// ---------------------------------------------------------------------------
__global__ __launch_bounds__(256) void gather_k(const float* __restrict__ bias,
                                                const int* __restrict__ sent,
                                                float* __restrict__ out) {
    int row = blockIdx.x;
    int bb = row >> 9;
    int s = row & 511;
    int tid = threadIdx.x;

    const float4* b4 = (const float4*)bias;
    float4 acc[4];
#pragma unroll
    for (int i = 0; i < 4; i++) acc[i] = b4[i * 256 + tid];

#pragma unroll
    for (int k = 0; k < FW; k++) {
        int p = s + k - 2;
        if (p >= 0 && p < SLEN) {
            int tok = __ldg(&sent[(bb << 9) + p]);
            const float4* col = (const float4*)(g_Wt + ((size_t)k * V + tok) * T);
#pragma unroll
            for (int i = 0; i < 4; i++) {
                float4 w = col[i * 256 + tid];
                acc[i].x += w.x; acc[i].y += w.y;
                acc[i].z += w.z; acc[i].w += w.w;
            }
        }
    }

    __shared__ float sv[256];
    __shared__ int   si[256];
    __shared__ float ss[256];

    // ---- pass A: row max m
    float vmax = -1e30f;
#pragma unroll
    for (int i = 0; i < 4; i++) {
        float* a = (float*)&acc[i];
#pragma unroll
        for (int j = 0; j < 4; j++) vmax = fmaxf(vmax, a[j]);
    }
    sv[tid] = vmax;
    __syncthreads();
#pragma unroll
    for (int off = 128; off > 0; off >>= 1) {
        if (tid < off) sv[tid] = fmaxf(sv[tid], sv[tid + off]);
        __syncthreads();
    }
    float m = sv[0];
    __syncthreads();

    // ---- pass B: S0 = sum exp(l - m)
    float s0 = 0.f;
#pragma unroll
    for (int i = 0; i < 4; i++) {
        float* a = (float*)&acc[i];
#pragma unroll
        for (int j = 0; j < 4; j++) s0 += expf(a[j] - m);
    }
    sv[tid] = s0;
    __syncthreads();
#pragma unroll
    for (int off = 128; off > 0; off >>= 1) {
        if (tid < off) sv[tid] += sv[tid + off];
        __syncthreads();
    }
    float c = logf(sv[0]);   // logS0 (ulp slack vs XLA is tie-invariant)
    __syncthreads();

    // ---- pass C: quantized lp, argmax(lp) first-index ties, entropy sum
    float lmax = -1e30f;
    int lidx = 0;
    float hs = 0.f;
#pragma unroll
    for (int i = 0; i < 4; i++) {
        float* a = (float*)&acc[i];
#pragma unroll
        for (int j = 0; j < 4; j++) {
            float d = a[j] - m;
            float lp = d - c;            // fp32 quantization — creates ref's ties
            float p = expf(lp);
            hs += p * lp;
            int t = i * 1024 + tid * 4 + j;   // ascending t per thread
            if (lp > lmax) { lmax = lp; lidx = t; }
        }
    }
    sv[tid] = lmax; si[tid] = lidx; ss[tid] = hs;
    __syncthreads();
#pragma unroll
    for (int off = 128; off > 0; off >>= 1) {
        if (tid < off) {
            float ov = sv[tid + off];
            int   oi = si[tid + off];
            if (ov > sv[tid] || (ov == sv[tid] && oi < si[tid])) {
                sv[tid] = ov; si[tid] = oi;
            }
            ss[tid] += ss[tid + off];
        }
        __syncthreads();
    }

    if (tid == 0) {
        out[row] = (float)si[0];        // new_seq
        out[NROWS + row] = sv[0];       // log_prob at argmax (quantized lp)
        g_rowent[row] = -ss[0];         // -sum_t p*log_p for this row
    }
}

// ---------------------------------------------------------------------------
// Kernel 3: deterministic entropy reduction
// ---------------------------------------------------------------------------
__global__ __launch_bounds__(256) void finalize_k(float* __restrict__ out) {
    __shared__ double sd[256];
    int tid = threadIdx.x;
    double a = 0.0;
    for (int i = tid; i < NROWS; i += 256) a += (double)g_rowent[i];
    sd[tid] = a;
    __syncthreads();
#pragma unroll
    for (int off = 128; off > 0; off >>= 1) {
        if (tid < off) sd[tid] += sd[tid + off];
        __syncthreads();
    }
    if (tid == 0)
        out[2 * NROWS] = (float)(sd[0] / ((double)NROWS * (double)T));
}

// ---------------------------------------------------------------------------
extern "C" void kernel_launch(void* const* d_in, const int* in_sizes, int n_in,
                              void* d_out, int out_size) {
    const float* W    = (const float*)d_in[0];   // (T, V, FW) f32
    const float* bias = (const float*)d_in[1];   // (T,) f32
    const int*   sent = (const int*)d_in[2];     // (B, S) int32
    float* out = (float*)d_out;                  // [newseq | logp | entropy]

    dim3 tb(32, 8);
    dim3 tg(CDIM / 32, T / 32);
    transpose_k<<<tg, tb>>>(W);
    gather_k<<<NROWS, 256>>>(bias, sent, out);
    finalize_k<<<1, 256>>>(out);
}

// round 3
// speedup vs baseline: 1.3859x; 1.3859x over previous
#include <cuda_runtime.h>
#include <cuda_fp16.h>

#define V 4096
#define T 4096
#define FW 5
#define BATCH 64
#define SLEN 512
#define NROWS (BATCH * SLEN)   // 32768
#define CDIM (V * FW)          // 20480
#define MARGIN 4e-4f
#define MAXCAND 64

// fp16 transposed weights Wt[k][v][t]  (t contiguous -> coalesced gathers)
__device__ __half g_Wt[(size_t)FW * V * T];
// Per-row entropy contributions
__device__ float g_rowent[NROWS];

// ---------------------------------------------------------------------------
// Kernel 1: transpose+convert W[t][v][k] (f32) -> Wt[k][v][t] (f16)
// ---------------------------------------------------------------------------
__global__ __launch_bounds__(256) void transpose_k(const float* __restrict__ W) {
    __shared__ float tile[32][33];
    int c0 = blockIdx.x << 5;
    int t0 = blockIdx.y << 5;
    int tx = threadIdx.x;   // 0..31
    int ty = threadIdx.y;   // 0..7

#pragma unroll
    for (int j = 0; j < 4; j++) {
        int t = t0 + ty + j * 8;
        tile[ty + j * 8][tx] = W[(size_t)t * CDIM + c0 + tx];
    }
    __syncthreads();
#pragma unroll
    for (int j = 0; j < 4; j++) {
        int c = c0 + ty + j * 8;
        int v = c / 5;
        int k = c - v * 5;
        g_Wt[((size_t)k * V + v) * T + t0 + tx] = __float2half(tile[tx][ty + j * 8]);
    }
}

// ---------------------------------------------------------------------------
// Kernel 2: one block per row (b,s). fp16 gathered logits; exact fp32 recheck
// (reading original W) for rows where the top gap < MARGIN, reproducing the
// reference's quantized log_softmax argmax with first-index tie-breaking.
// Thread tid owns t in {c*2048 + tid*8 + j : c<2, j<8}  (coalesced uint4 loads)
// ---------------------------------------------------------------------------
__global__ __launch_bounds__(256) void gather_k(const float* __restrict__ bias,
                                                const int* __restrict__ sent,
                                                const float* __restrict__ W,
                                                float* __restrict__ out) {
    int row = blockIdx.x;
    int bb = row >> 9;
    int s = row & 511;
    int tid = threadIdx.x;

    __shared__ float sv[256];
    __shared__ float ss[256];
    __shared__ int cand_t[MAXCAND];
    __shared__ int cand_n;

    // accumulate logits in fp32, fp16 weights
    float acc[16];
#pragma unroll
    for (int c = 0; c < 2; c++) {
        const float4* b4 = (const float4*)(bias + c * 2048 + tid * 8);
        float4 b0 = b4[0], b1 = b4[1];
        acc[c * 8 + 0] = b0.x; acc[c * 8 + 1] = b0.y; acc[c * 8 + 2] = b0.z; acc[c * 8 + 3] = b0.w;
        acc[c * 8 + 4] = b1.x; acc[c * 8 + 5] = b1.y; acc[c * 8 + 6] = b1.z; acc[c * 8 + 7] = b1.w;
    }

#pragma unroll
    for (int k = 0; k < FW; k++) {
        int p = s + k - 2;
        if (p >= 0 && p < SLEN) {
            int tok = __ldg(&sent[(bb << 9) + p]);
            const __half* col = g_Wt + ((size_t)k * V + tok) * T;
#pragma unroll
            for (int c = 0; c < 2; c++) {
                uint4 h = *(const uint4*)(col + c * 2048 + tid * 8);
                const __half2* h2 = (const __half2*)&h;
#pragma unroll
                for (int q = 0; q < 4; q++) {
                    float2 f = __half22float2(h2[q]);
                    acc[c * 8 + q * 2 + 0] += f.x;
                    acc[c * 8 + q * 2 + 1] += f.y;
                }
            }
        }
    }

    // ---- max reduce (value only)
    float vmax = acc[0];
#pragma unroll
    for (int i = 1; i < 16; i++) vmax = fmaxf(vmax, acc[i]);
    sv[tid] = vmax;
    if (tid == 0) cand_n = 0;
    __syncthreads();
#pragma unroll
    for (int off = 128; off > 0; off >>= 1) {
        if (tid < off) sv[tid] = fmaxf(sv[tid], sv[tid + off]);
        __syncthreads();
    }
    float mprime = sv[0];
    __syncthreads();

    // ---- single pass: S0, S1, candidate collection
    float s0 = 0.f, s1 = 0.f;
    float thr = mprime - MARGIN;
#pragma unroll
    for (int c = 0; c < 2; c++) {
#pragma unroll
        for (int j = 0; j < 8; j++) {
            float l = acc[c * 8 + j];
            float d = l - mprime;
            float e = expf(d);
            s0 += e;
            s1 += d * e;
            if (l >= thr) {
                int idx = atomicAdd(&cand_n, 1);
                if (idx < MAXCAND) cand_t[idx] = c * 2048 + tid * 8 + j;
            }
        }
    }
    sv[tid] = s0; ss[tid] = s1;
    __syncthreads();
#pragma unroll
    for (int off = 128; off > 0; off >>= 1) {
        if (tid < off) { sv[tid] += sv[tid + off]; ss[tid] += ss[tid + off]; }
        __syncthreads();
    }

    if (tid == 0) {
        float S0 = sv[0], S1 = ss[0];
        float c0 = logf(S0);
        int nc = cand_n < MAXCAND ? cand_n : MAXCAND;

        // exact fp32 logits for candidates (reference summation order)
        float lex[8];   // registers for the common case; spill path below
        float m = -1e30f;
        for (int i = 0; i < nc; i++) {
            int t = cand_t[i];
            float l = __ldg(&bias[t]);
#pragma unroll
            for (int k = 0; k < FW; k++) {
                int p = s + k - 2;
                if (p >= 0 && p < SLEN) {
                    int tok = __ldg(&sent[(bb << 9) + p]);
                    l += __ldg(&W[(size_t)t * CDIM + tok * 5 + k]);
                }
            }
            if (i < 8) lex[i] = l;
            else ss[i] = l;          // overflow stash in smem (rare)
            m = fmaxf(m, l);
        }
        // c consistent with exact m:  S0_exact ~= S0 * e^(m'-m)
        float cc = c0 + (mprime - m);

        float bestlp = -1e30f;
        int bestt = 0x7fffffff;
        for (int i = 0; i < nc; i++) {
            float l = (i < 8) ? lex[i] : ss[i];
            float d = l - m;         // fp32, matches reference 'shifted'
            float lp = d - cc;       // fp32 quantization -> reference ties
            int t = cand_t[i];
            if (lp > bestlp || (lp == bestlp && t < bestt)) { bestlp = lp; bestt = t; }
        }

        out[row] = (float)bestt;          // new_seq
        out[NROWS + row] = bestlp;        // log_prob at argmax
        g_rowent[row] = c0 - S1 / S0;     // -sum_t p*lp (row entropy)
    }
}

// ---------------------------------------------------------------------------
// Kernel 3: deterministic entropy reduction
// ---------------------------------------------------------------------------
__global__ __launch_bounds__(256) void finalize_k(float* __restrict__ out) {
    __shared__ double sd[256];
    int tid = threadIdx.x;
    double a = 0.0;
    for (int i = tid; i < NROWS; i += 256) a += (double)g_rowent[i];
    sd[tid] = a;
    __syncthreads();
#pragma unroll
    for (int off = 128; off > 0; off >>= 1) {
        if (tid < off) sd[tid] += sd[tid + off];
        __syncthreads();
    }
    if (tid == 0)
        out[2 * NROWS] = (float)(sd[0] / ((double)NROWS * (double)T));
}

// ---------------------------------------------------------------------------
extern "C" void kernel_launch(void* const* d_in, const int* in_sizes, int n_in,
                              void* d_out, int out_size) {
    const float* W    = (const float*)d_in[0];   // (T, V, FW) f32
    const float* bias = (const float*)d_in[1];   // (T,) f32
    const int*   sent = (const int*)d_in[2];     // (B, S) int32
    float* out = (float*)d_out;                  // [newseq | logp | entropy]

    dim3 tb(32, 8);
    dim3 tg(CDIM / 32, T / 32);
    transpose_k<<<tg, tb>>>(W);
    gather_k<<<NROWS, 256>>>(bias, sent, W, out);
    finalize_k<<<1, 256>>>(out);
}